// round 2
// baseline (speedup 1.0000x reference)
#include <cuda_runtime.h>
#include <math.h>

#define B 32
#define C 128
#define NN 4096
#define HEADS 4
#define DH 32
#define HIDDEN 128
#define QSCALE 0.17677669529663687f   /* 32^-0.5 */
#define GEPS 1e-5f

typedef unsigned long long u64;

union F2U { u64 u; float2 f; };

__device__ __forceinline__ float2 unpack2(u64 v) { F2U t; t.u = v; return t.f; }

__device__ __forceinline__ u64 ffma2(u64 a, u64 b, u64 c) {
    asm("fma.rn.f32x2 %0, %1, %2, %0;" : "+l"(c) : "l"(a), "l"(b));
    return c;
}

// ---------------- scratch ----------------
__device__ float g_qkv[(size_t)B * 384 * NN];   // rows 0-127 q (softmaxed in place), 128-255 k, 256-383 v
__device__ float g_ctx[B * HEADS * DH * DH];
__device__ float g_M[B * HIDDEN * HIDDEN];
__device__ float g_y[(size_t)B * C * NN];
__device__ float g_sum[B];
__device__ float g_sumsq[B];

// ---------------- K0 ----------------
__global__ void k0_zero() {
    int t = threadIdx.x;
    if (t < B) { g_sum[t] = 0.f; g_sumsq[t] = 0.f; }
}

// ---------------- K1: qkv projection, 128x128x128 tiles, f32x2 ----------------
// grid (32 ncol, 3 rowtile, 32 b), 256 threads, 8x8 per thread
__global__ void __launch_bounds__(256) k1_proj(
    const float* __restrict__ x,
    const float* __restrict__ Wq,
    const float* __restrict__ Wk,
    const float* __restrict__ Wv)
{
    __shared__ float sA[8 * 256];   // [kk][2*r] duplicated pairs
    __shared__ float sB[8 * 128];   // [kk][col]

    const int b  = blockIdx.z;
    const int rowtile = blockIdx.y;
    const int n0 = blockIdx.x * 128;
    const int tid = threadIdx.x;
    const int tx = tid & 15, ty = tid >> 4;
    const int c0 = tx * 8, r0 = ty * 8;

    const float* Wp = (rowtile == 0) ? Wq : ((rowtile == 1) ? Wk : Wv);
    const float* xb = x + (size_t)b * C * NN + n0;

    const int lr = tid & 127, lh = tid >> 7;       // A loader: row, k-half
    const int bk = tid >> 5,  bj = (tid & 31) * 4; // B loader: kk, col4

    u64 acc[8][4];
#pragma unroll
    for (int i = 0; i < 8; i++)
#pragma unroll
        for (int j = 0; j < 4; j++) acc[i][j] = 0ull;

    for (int kt = 0; kt < 16; kt++) {
        const int k0 = kt * 8;
        float4 wv = *(const float4*)&Wp[lr * 128 + k0 + lh * 4];
        float4 xv = *(const float4*)&xb[(size_t)(k0 + bk) * NN + bj];
        __syncthreads();
        *(float2*)&sA[(lh * 4 + 0) * 256 + 2 * lr] = make_float2(wv.x, wv.x);
        *(float2*)&sA[(lh * 4 + 1) * 256 + 2 * lr] = make_float2(wv.y, wv.y);
        *(float2*)&sA[(lh * 4 + 2) * 256 + 2 * lr] = make_float2(wv.z, wv.z);
        *(float2*)&sA[(lh * 4 + 3) * 256 + 2 * lr] = make_float2(wv.w, wv.w);
        *(float4*)&sB[bk * 128 + bj] = xv;
        __syncthreads();
#pragma unroll
        for (int kk = 0; kk < 8; kk++) {
            const float* bp = &sB[kk * 128 + c0];
            ulonglong2 bb0 = *(const ulonglong2*)bp;
            ulonglong2 bb1 = *(const ulonglong2*)(bp + 4);
#pragma unroll
            for (int i = 0; i < 8; i++) {
                u64 av = *(const u64*)&sA[kk * 256 + 2 * (r0 + i)];
                acc[i][0] = ffma2(av, bb0.x, acc[i][0]);
                acc[i][1] = ffma2(av, bb0.y, acc[i][1]);
                acc[i][2] = ffma2(av, bb1.x, acc[i][2]);
                acc[i][3] = ffma2(av, bb1.y, acc[i][3]);
            }
        }
    }

    float* outp = g_qkv + ((size_t)b * 384 + rowtile * 128) * NN + n0;
#pragma unroll
    for (int i = 0; i < 8; i++) {
        int r = r0 + i;
        float2 f0 = unpack2(acc[i][0]);
        float2 f1 = unpack2(acc[i][1]);
        float2 f2 = unpack2(acc[i][2]);
        float2 f3 = unpack2(acc[i][3]);
        *(float4*)&outp[(size_t)r * NN + c0]     = make_float4(f0.x, f0.y, f1.x, f1.y);
        *(float4*)&outp[(size_t)r * NN + c0 + 4] = make_float4(f2.x, f2.y, f3.x, f3.y);
    }
}

// ---------------- KQ: q softmax over d, in place ----------------
// grid (128 ntiles, 32 b), 128 threads; tile [128 d][32 cols]
__global__ void __launch_bounds__(128) kq_soft()
{
    __shared__ float s[128 * 36];
    const int b = blockIdx.y;
    const int n0 = blockIdx.x * 32;
    const int tid = threadIdx.x;
    float* base = g_qkv + (size_t)b * 384 * NN + n0;

#pragma unroll
    for (int j = 0; j < 8; j++) {
        float4 t = *(const float4*)&base[(size_t)tid * NN + j * 4];
        *(float4*)&s[tid * 36 + j * 4] = t;
    }
    __syncthreads();

    const int h = tid >> 5, col = tid & 31;
    float mx = -1e30f;
#pragma unroll
    for (int d = 0; d < 32; d++) mx = fmaxf(mx, s[(h * 32 + d) * 36 + col]);
    float e[32];
    float sum = 0.f;
#pragma unroll
    for (int d = 0; d < 32; d++) {
        e[d] = __expf(s[(h * 32 + d) * 36 + col] - mx);
        sum += e[d];
    }
    float inv = QSCALE / sum;
#pragma unroll
    for (int d = 0; d < 32; d++)
        base[(size_t)(h * 32 + d) * NN + col] = e[d] * inv;
}

// ---------------- K2: k row-softmax + ctx = softmax(k) @ v^T ----------------
__global__ void __launch_bounds__(256) k2_ctx()
{
    const int bh = blockIdx.x;
    const int b = bh >> 2, h = bh & 3;
    const float* kb = g_qkv + ((size_t)b * 384 + 128 + h * 32) * NN;
    const float* vb = g_qkv + ((size_t)b * 384 + 256 + h * 32) * NN;

    __shared__ float rmax[32], rsum[32];
    __shared__ float sK[32 * 128];
    __shared__ float sVT[128 * 36];

    const int tid = threadIdx.x;
    const int w = tid >> 5, lane = tid & 31;

    for (int rr = 0; rr < 4; rr++) {
        int row = w * 4 + rr;
        const float4* kr4 = (const float4*)(kb + (size_t)row * NN);
        float4 mv = make_float4(-1e30f, -1e30f, -1e30f, -1e30f);
#pragma unroll 4
        for (int j = 0; j < 32; j++) {
            float4 t = kr4[lane + j * 32];
            mv.x = fmaxf(mv.x, t.x); mv.y = fmaxf(mv.y, t.y);
            mv.z = fmaxf(mv.z, t.z); mv.w = fmaxf(mv.w, t.w);
        }
        float mx = fmaxf(fmaxf(mv.x, mv.y), fmaxf(mv.z, mv.w));
#pragma unroll
        for (int o = 16; o; o >>= 1) mx = fmaxf(mx, __shfl_xor_sync(0xffffffffu, mx, o));
        float s = 0.f;
#pragma unroll 4
        for (int j = 0; j < 32; j++) {
            float4 t = kr4[lane + j * 32];
            s += __expf(t.x - mx) + __expf(t.y - mx) + __expf(t.z - mx) + __expf(t.w - mx);
        }
#pragma unroll
        for (int o = 16; o; o >>= 1) s += __shfl_xor_sync(0xffffffffu, s, o);
        if (lane == 0) { rmax[row] = mx; rsum[row] = s; }
    }
    __syncthreads();

    const int d  = tid >> 3;
    const int e0 = (tid & 7) * 4;
    const int ld_row = tid >> 3;
    const int ld_c   = (tid & 7) * 16;
    float4 acc = make_float4(0.f, 0.f, 0.f, 0.f);

    for (int c0 = 0; c0 < NN; c0 += 128) {
        __syncthreads();
        {
            const float* kr = kb + (size_t)ld_row * NN + c0 + ld_c;
            float m = rmax[ld_row];
#pragma unroll
            for (int q4 = 0; q4 < 4; q4++) {
                float4 t = *(const float4*)(kr + q4 * 4);
                int base = ld_row * 128 + ld_c + q4 * 4;
                sK[base + 0] = __expf(t.x - m);
                sK[base + 1] = __expf(t.y - m);
                sK[base + 2] = __expf(t.z - m);
                sK[base + 3] = __expf(t.w - m);
            }
            const float* vr = vb + (size_t)ld_row * NN + c0 + ld_c;
#pragma unroll
            for (int q4 = 0; q4 < 4; q4++) {
                float4 t = *(const float4*)(vr + q4 * 4);
                int nc = ld_c + q4 * 4;
                sVT[(nc + 0) * 36 + ld_row] = t.x;
                sVT[(nc + 1) * 36 + ld_row] = t.y;
                sVT[(nc + 2) * 36 + ld_row] = t.z;
                sVT[(nc + 3) * 36 + ld_row] = t.w;
            }
        }
        __syncthreads();
#pragma unroll 4
        for (int n = 0; n < 128; n++) {
            float kd = sK[d * 128 + n];
            float4 vv = *(const float4*)&sVT[n * 36 + e0];
            acc.x += kd * vv.x; acc.y += kd * vv.y;
            acc.z += kd * vv.z; acc.w += kd * vv.w;
        }
    }
    float inv = 1.0f / rsum[d];
    acc.x *= inv; acc.y *= inv; acc.z *= inv; acc.w *= inv;
    *(float4*)&g_ctx[((size_t)bh * 32 + d) * 32 + e0] = acc;
}

// ---------------- K3: fold M_b = Wo @ blockdiag(ctx^T) ----------------
// grid (4, 32): 32 o-rows per block
__global__ void __launch_bounds__(256) k3_fold(const float* __restrict__ Wo)
{
    const int b = blockIdx.y;
    const int og = blockIdx.x * 32;
    __shared__ float sctx[HEADS * DH * DH];
    const int tid = threadIdx.x;
#pragma unroll
    for (int rr = 0; rr < 4; rr++) {
        int idx = tid + rr * 256;
        *(float4*)&sctx[idx * 4] = *(const float4*)&g_ctx[(size_t)b * 4096 + idx * 4];
    }
    __syncthreads();

    const int o = og + (tid >> 3);
    const int colg = (tid & 7) * 16;
    const int h = colg >> 5;

    float wo[32];
#pragma unroll
    for (int q4 = 0; q4 < 8; q4++) {
        float4 t = *(const float4*)&Wo[o * 128 + h * 32 + q4 * 4];
        wo[q4 * 4 + 0] = t.x; wo[q4 * 4 + 1] = t.y;
        wo[q4 * 4 + 2] = t.z; wo[q4 * 4 + 3] = t.w;
    }
    float* Mout = g_M + (size_t)b * HIDDEN * HIDDEN + o * HIDDEN;
#pragma unroll
    for (int cc = 0; cc < 16; cc++) {
        int col = colg + cc;
        int dd = col & 31;
        float s = 0.f;
#pragma unroll
        for (int q4 = 0; q4 < 8; q4++) {
            float4 cv = *(const float4*)&sctx[(h * 32 + dd) * 32 + q4 * 4];
            s += wo[q4 * 4 + 0] * cv.x + wo[q4 * 4 + 1] * cv.y
               + wo[q4 * 4 + 2] * cv.z + wo[q4 * 4 + 3] * cv.w;
        }
        Mout[col] = s;
    }
}

// ---------------- K4: y = M_b @ softq + bo, stats; f32x2, 128x128 tiles ----------------
// grid (32 ncol, 32 b), 256 threads
__global__ void __launch_bounds__(256) k4_out(const float* __restrict__ bo)
{
    __shared__ float sA[8 * 256];
    __shared__ float sB[8 * 128];
    __shared__ float redS[8], redQ[8];

    const int b  = blockIdx.y;
    const int n0 = blockIdx.x * 128;
    const int tid = threadIdx.x;
    const int tx = tid & 15, ty = tid >> 4;
    const int c0 = tx * 8, r0 = ty * 8;

    const float* Mb = g_M + (size_t)b * HIDDEN * HIDDEN;
    const float* qb = g_qkv + (size_t)b * 384 * NN + n0;

    const int lr = tid & 127, lh = tid >> 7;
    const int bk = tid >> 5,  bj = (tid & 31) * 4;

    u64 acc[8][4];
#pragma unroll
    for (int i = 0; i < 8; i++)
#pragma unroll
        for (int j = 0; j < 4; j++) acc[i][j] = 0ull;

    for (int kt = 0; kt < 16; kt++) {
        const int k0 = kt * 8;
        float4 wv = *(const float4*)&Mb[lr * 128 + k0 + lh * 4];
        float4 xv = *(const float4*)&qb[(size_t)(k0 + bk) * NN + bj];
        __syncthreads();
        *(float2*)&sA[(lh * 4 + 0) * 256 + 2 * lr] = make_float2(wv.x, wv.x);
        *(float2*)&sA[(lh * 4 + 1) * 256 + 2 * lr] = make_float2(wv.y, wv.y);
        *(float2*)&sA[(lh * 4 + 2) * 256 + 2 * lr] = make_float2(wv.z, wv.z);
        *(float2*)&sA[(lh * 4 + 3) * 256 + 2 * lr] = make_float2(wv.w, wv.w);
        *(float4*)&sB[bk * 128 + bj] = xv;
        __syncthreads();
#pragma unroll
        for (int kk = 0; kk < 8; kk++) {
            const float* bp = &sB[kk * 128 + c0];
            ulonglong2 bb0 = *(const ulonglong2*)bp;
            ulonglong2 bb1 = *(const ulonglong2*)(bp + 4);
#pragma unroll
            for (int i = 0; i < 8; i++) {
                u64 av = *(const u64*)&sA[kk * 256 + 2 * (r0 + i)];
                acc[i][0] = ffma2(av, bb0.x, acc[i][0]);
                acc[i][1] = ffma2(av, bb0.y, acc[i][1]);
                acc[i][2] = ffma2(av, bb1.x, acc[i][2]);
                acc[i][3] = ffma2(av, bb1.y, acc[i][3]);
            }
        }
    }

    float* outp = g_y + (size_t)b * C * NN + n0;
    float lsum = 0.f, lsq = 0.f;
#pragma unroll
    for (int i = 0; i < 8; i++) {
        int r = r0 + i;
        float bb = bo[r];
        float2 f0 = unpack2(acc[i][0]);
        float2 f1 = unpack2(acc[i][1]);
        float2 f2 = unpack2(acc[i][2]);
        float2 f3 = unpack2(acc[i][3]);
        float v[8] = { f0.x + bb, f0.y + bb, f1.x + bb, f1.y + bb,
                       f2.x + bb, f2.y + bb, f3.x + bb, f3.y + bb };
        *(float4*)&outp[(size_t)r * NN + c0]     = make_float4(v[0], v[1], v[2], v[3]);
        *(float4*)&outp[(size_t)r * NN + c0 + 4] = make_float4(v[4], v[5], v[6], v[7]);
#pragma unroll
        for (int j = 0; j < 8; j++) { lsum += v[j]; lsq += v[j] * v[j]; }
    }
    const int w = tid >> 5, lane = tid & 31;
#pragma unroll
    for (int o = 16; o; o >>= 1) {
        lsum += __shfl_xor_sync(0xffffffffu, lsum, o);
        lsq  += __shfl_xor_sync(0xffffffffu, lsq,  o);
    }
    if (lane == 0) { redS[w] = lsum; redQ[w] = lsq; }
    __syncthreads();
    if (tid == 0) {
        float s = 0.f, q = 0.f;
#pragma unroll
        for (int i = 0; i < 8; i++) { s += redS[i]; q += redQ[i]; }
        atomicAdd(&g_sum[b], s);
        atomicAdd(&g_sumsq[b], q);
    }
}

// ---------------- K5: GroupNorm, float4 ----------------
__global__ void __launch_bounds__(256) k5_norm(
    const float* __restrict__ gn_w, const float* __restrict__ gn_b,
    float* __restrict__ out)
{
    int i4 = blockIdx.x * 256 + threadIdx.x;   // 4,194,304 float4s
    int b = i4 >> 17;
    int c = (i4 >> 10) & 127;
    const float cn = (float)(C * NN);
    float mu = g_sum[b] / cn;
    float var = g_sumsq[b] / cn - mu * mu;
    float is = rsqrtf(var + GEPS);
    float w = gn_w[c] * is, bb = gn_b[c] - mu * w;
    float4 v = *(const float4*)&g_y[(size_t)i4 * 4];
    v.x = v.x * w + bb; v.y = v.y * w + bb;
    v.z = v.z * w + bb; v.w = v.w * w + bb;
    *(float4*)&out[(size_t)i4 * 4] = v;
}

// ---------------- launch ----------------
extern "C" void kernel_launch(void* const* d_in, const int* in_sizes, int n_in,
                              void* d_out, int out_size)
{
    const float* x  = (const float*)d_in[0];
    const float* Wq = (const float*)d_in[1];
    const float* Wk = (const float*)d_in[2];
    const float* Wv = (const float*)d_in[3];
    const float* Wo = (const float*)d_in[4];
    const float* bo = (const float*)d_in[5];
    const float* gw = (const float*)d_in[6];
    const float* gb = (const float*)d_in[7];
    float* out = (float*)d_out;

    k0_zero<<<1, 32>>>();
    k1_proj<<<dim3(32, 3, 32), 256>>>(x, Wq, Wk, Wv);
    kq_soft<<<dim3(128, 32), 128>>>();
    k2_ctx<<<128, 256>>>();
    k3_fold<<<dim3(4, 32), 256>>>(Wo);
    k4_out<<<dim3(32, 32), 256>>>(bo);
    k5_norm<<<16384, 256>>>(gw, gb, out);
}

// round 3
// speedup vs baseline: 1.4801x; 1.4801x over previous
#include <cuda_runtime.h>
#include <math.h>

#define B 32
#define C 128
#define NN 4096
#define HEADS 4
#define DH 32
#define HIDDEN 128
#define QSCALE 0.17677669529663687f   /* 32^-0.5 */
#define GEPS 1e-5f

// ---------------- scratch ----------------
__device__ float g_qkv[(size_t)B * 384 * NN];  // 0-127 q (softmaxed in place), 128-255 k, 256-383 v
__device__ float g_ctx[B * HEADS * DH * DH];   // UNNORMALIZED ctx partial sums
__device__ float g_rsum[B * HIDDEN];           // per (b, h*32+d) sum of exp(k)
__device__ float g_M[B * HIDDEN * HIDDEN];
__device__ float g_y[(size_t)B * C * NN];
__device__ float g_sum[B];
__device__ float g_sumsq[B];

// ---------------- K0: zero accumulators ----------------
__global__ void __launch_bounds__(256) k0_zero() {
    int gid = blockIdx.x * 256 + threadIdx.x;
    float4 z = make_float4(0.f, 0.f, 0.f, 0.f);
    if (gid < 32768) ((float4*)g_ctx)[gid] = z;      // 131072 floats
    if (gid < 1024)  ((float4*)g_rsum)[gid] = z;     // 4096 floats
    if (gid < 32) { g_sum[gid] = 0.f; g_sumsq[gid] = 0.f; }
}

// ---------------- K1: qkv projection 128x128x128 tiles + fused q softmax ----------------
// grid (32 ncol, 3 rowtile, 32 b), 256 threads, 8x8 per thread, scalar FFMA
__global__ void __launch_bounds__(256) k1_proj(
    const float* __restrict__ x,
    const float* __restrict__ Wq,
    const float* __restrict__ Wk,
    const float* __restrict__ Wv)
{
    extern __shared__ float smem[];
    float* sA = smem;            // [8][128]
    float* sB = smem + 1024;     // [8][128]
    float* stage = smem;         // reused: [128][132] after mainloop

    const int b  = blockIdx.z;
    const int rowtile = blockIdx.y;
    const int n0 = blockIdx.x * 128;
    const int tid = threadIdx.x;
    const int tx = tid & 15, ty = tid >> 4;
    const int c0 = tx * 8, r0 = ty * 8;

    const float* Wp = (rowtile == 0) ? Wq : ((rowtile == 1) ? Wk : Wv);
    const float* xb = x + (size_t)b * C * NN + n0;

    const int arow = tid >> 1, akq = tid & 1;       // A loader
    const int bk = tid >> 5,  bj = (tid & 31) * 4;  // B loader

    float acc[8][8];
#pragma unroll
    for (int i = 0; i < 8; i++)
#pragma unroll
        for (int j = 0; j < 8; j++) acc[i][j] = 0.f;

    const float4* sA4 = (const float4*)sA;
    const float4* sB4 = (const float4*)sB;

    for (int kt = 0; kt < 16; kt++) {
        const int k0 = kt * 8;
        float4 wv = *(const float4*)&Wp[arow * 128 + k0 + akq * 4];
        float4 xv = *(const float4*)&xb[(size_t)(k0 + bk) * NN + bj];
        __syncthreads();
        sA[(akq * 4 + 0) * 128 + arow] = wv.x;
        sA[(akq * 4 + 1) * 128 + arow] = wv.y;
        sA[(akq * 4 + 2) * 128 + arow] = wv.z;
        sA[(akq * 4 + 3) * 128 + arow] = wv.w;
        *(float4*)&sB[bk * 128 + bj] = xv;
        __syncthreads();
#pragma unroll
        for (int kk = 0; kk < 8; kk++) {
            float4 a0 = sA4[kk * 32 + ty * 2];
            float4 a1 = sA4[kk * 32 + ty * 2 + 1];
            float4 b0 = sB4[kk * 32 + tx * 2];
            float4 b1 = sB4[kk * 32 + tx * 2 + 1];
            float av[8] = { a0.x, a0.y, a0.z, a0.w, a1.x, a1.y, a1.z, a1.w };
            float bv[8] = { b0.x, b0.y, b0.z, b0.w, b1.x, b1.y, b1.z, b1.w };
#pragma unroll
            for (int i = 0; i < 8; i++)
#pragma unroll
                for (int j = 0; j < 8; j++)
                    acc[i][j] += av[i] * bv[j];
        }
    }

    if (rowtile != 0) {
        float* outp = g_qkv + ((size_t)b * 384 + rowtile * 128) * NN + n0;
#pragma unroll
        for (int i = 0; i < 8; i++) {
            int r = r0 + i;
            *(float4*)&outp[(size_t)r * NN + c0] =
                make_float4(acc[i][0], acc[i][1], acc[i][2], acc[i][3]);
            *(float4*)&outp[(size_t)r * NN + c0 + 4] =
                make_float4(acc[i][4], acc[i][5], acc[i][6], acc[i][7]);
        }
        return;
    }

    // rowtile 0 = q: stage to smem, softmax over d per (h, col), write coalesced
    __syncthreads();
#pragma unroll
    for (int i = 0; i < 8; i++) {
        int r = r0 + i;
        *(float4*)&stage[r * 132 + c0] =
            make_float4(acc[i][0], acc[i][1], acc[i][2], acc[i][3]);
        *(float4*)&stage[r * 132 + c0 + 4] =
            make_float4(acc[i][4], acc[i][5], acc[i][6], acc[i][7]);
    }
    __syncthreads();

    float* outq = g_qkv + (size_t)b * 384 * NN + n0;
#pragma unroll
    for (int t = tid; t < 512; t += 256) {
        const int col = t & 127;
        const int h = t >> 7;
        float sum = 0.f;
#pragma unroll
        for (int d = 0; d < 32; d++) {
            float* p = &stage[(h * 32 + d) * 132 + col];
            float e = __expf(*p);
            *p = e;
            sum += e;
        }
        float inv = QSCALE / sum;
#pragma unroll
        for (int d = 0; d < 32; d++)
            outq[(size_t)(h * 32 + d) * NN + col] = stage[(h * 32 + d) * 132 + col] * inv;
    }
}

// ---------------- K2: partial ctx = exp(k) @ v^T and partial rowsum ----------------
// grid (8 chunks, 128 bh), 256 threads; chunk = 512 cols; atomics into g_ctx/g_rsum
__global__ void __launch_bounds__(256) k2_ctx()
{
    const int bh = blockIdx.y;
    const int b = bh >> 2, h = bh & 3;
    const int cbase = blockIdx.x * 512;
    const float* kb = g_qkv + ((size_t)b * 384 + 128 + h * 32) * NN + cbase;
    const float* vb = g_qkv + ((size_t)b * 384 + 256 + h * 32) * NN + cbase;

    __shared__ float sK[32 * 128];     // exp'd k sub-tile [d][n]
    __shared__ float sVT[128 * 36];    // v sub-tile transposed [n][e]

    const int tid = threadIdx.x;
    const int d  = tid >> 3;
    const int e0 = (tid & 7) * 4;
    const int ld_row = tid >> 3;          // 0..31
    const int ld_c   = (tid & 7) * 16;    // 0..112

    float4 acc = make_float4(0.f, 0.f, 0.f, 0.f);
    float lsum = 0.f;

    for (int c0 = 0; c0 < 512; c0 += 128) {
        __syncthreads();
        {
            const float* kr = kb + (size_t)ld_row * NN + c0 + ld_c;
#pragma unroll
            for (int q4 = 0; q4 < 4; q4++) {
                float4 t = *(const float4*)(kr + q4 * 4);
                float e0v = __expf(t.x), e1v = __expf(t.y);
                float e2v = __expf(t.z), e3v = __expf(t.w);
                int base = ld_row * 128 + ld_c + q4 * 4;
                sK[base + 0] = e0v; sK[base + 1] = e1v;
                sK[base + 2] = e2v; sK[base + 3] = e3v;
                lsum += e0v + e1v + e2v + e3v;
            }
            const float* vr = vb + (size_t)ld_row * NN + c0 + ld_c;
#pragma unroll
            for (int q4 = 0; q4 < 4; q4++) {
                float4 t = *(const float4*)(vr + q4 * 4);
                int nc = ld_c + q4 * 4;
                sVT[(nc + 0) * 36 + ld_row] = t.x;
                sVT[(nc + 1) * 36 + ld_row] = t.y;
                sVT[(nc + 2) * 36 + ld_row] = t.z;
                sVT[(nc + 3) * 36 + ld_row] = t.w;
            }
        }
        __syncthreads();
#pragma unroll 4
        for (int n = 0; n < 128; n++) {
            float kd = sK[d * 128 + n];
            float4 vv = *(const float4*)&sVT[n * 36 + e0];
            acc.x += kd * vv.x; acc.y += kd * vv.y;
            acc.z += kd * vv.z; acc.w += kd * vv.w;
        }
    }

    // rowsum: reduce across the 8 threads sharing ld_row (lane groups of 8)
#pragma unroll
    for (int o = 4; o; o >>= 1) lsum += __shfl_xor_sync(0xffffffffu, lsum, o);
    if ((tid & 7) == 0)
        atomicAdd(&g_rsum[b * HIDDEN + h * 32 + ld_row], lsum);

    float* cp = &g_ctx[((size_t)bh * 32 + d) * 32 + e0];
    atomicAdd(cp + 0, acc.x);
    atomicAdd(cp + 1, acc.y);
    atomicAdd(cp + 2, acc.z);
    atomicAdd(cp + 3, acc.w);
}

// ---------------- K3: M_b = Wo @ blockdiag(ctx^T / rsum) ----------------
// grid (4, 32): 32 o-rows per block
__global__ void __launch_bounds__(256) k3_fold(const float* __restrict__ Wo)
{
    const int b = blockIdx.y;
    const int og = blockIdx.x * 32;
    __shared__ float sctx[HEADS * DH * DH];
    __shared__ float sinv[HIDDEN];
    const int tid = threadIdx.x;
#pragma unroll
    for (int rr = 0; rr < 4; rr++) {
        int idx = tid + rr * 256;
        *(float4*)&sctx[idx * 4] = *(const float4*)&g_ctx[(size_t)b * 4096 + idx * 4];
    }
    if (tid < 128) sinv[tid] = 1.0f / g_rsum[b * HIDDEN + tid];
    __syncthreads();

    const int o = og + (tid >> 3);
    const int colg = (tid & 7) * 16;
    const int h = colg >> 5;

    float wo[32];
#pragma unroll
    for (int q4 = 0; q4 < 8; q4++) {
        float4 t = *(const float4*)&Wo[o * 128 + h * 32 + q4 * 4];
        wo[q4 * 4 + 0] = t.x; wo[q4 * 4 + 1] = t.y;
        wo[q4 * 4 + 2] = t.z; wo[q4 * 4 + 3] = t.w;
    }
    float* Mout = g_M + (size_t)b * HIDDEN * HIDDEN + o * HIDDEN;
#pragma unroll
    for (int cc = 0; cc < 16; cc++) {
        int col = colg + cc;
        int dd = col & 31;
        float s = 0.f;
#pragma unroll
        for (int q4 = 0; q4 < 8; q4++) {
            float4 cv = *(const float4*)&sctx[(h * 32 + dd) * 32 + q4 * 4];
            s += wo[q4 * 4 + 0] * cv.x + wo[q4 * 4 + 1] * cv.y
               + wo[q4 * 4 + 2] * cv.z + wo[q4 * 4 + 3] * cv.w;
        }
        Mout[col] = s * sinv[col];
    }
}

// ---------------- K4: y = M_b @ softq + bo, + stats ----------------
// grid (32 ncol, 32 b), 256 threads, 8x8 per thread scalar
__global__ void __launch_bounds__(256) k4_out(const float* __restrict__ bo)
{
    __shared__ float sA[8 * 128];
    __shared__ float sB[8 * 128];
    __shared__ float redS[8], redQ[8];

    const int b  = blockIdx.y;
    const int n0 = blockIdx.x * 128;
    const int tid = threadIdx.x;
    const int tx = tid & 15, ty = tid >> 4;
    const int c0 = tx * 8, r0 = ty * 8;

    const float* Mb = g_M + (size_t)b * HIDDEN * HIDDEN;
    const float* qb = g_qkv + (size_t)b * 384 * NN + n0;

    const int arow = tid >> 1, akq = tid & 1;
    const int bk = tid >> 5,  bj = (tid & 31) * 4;

    float acc[8][8];
#pragma unroll
    for (int i = 0; i < 8; i++)
#pragma unroll
        for (int j = 0; j < 8; j++) acc[i][j] = 0.f;

    const float4* sA4 = (const float4*)sA;
    const float4* sB4 = (const float4*)sB;

    for (int kt = 0; kt < 16; kt++) {
        const int k0 = kt * 8;
        float4 wv = *(const float4*)&Mb[arow * 128 + k0 + akq * 4];
        float4 xv = *(const float4*)&qb[(size_t)(k0 + bk) * NN + bj];
        __syncthreads();
        sA[(akq * 4 + 0) * 128 + arow] = wv.x;
        sA[(akq * 4 + 1) * 128 + arow] = wv.y;
        sA[(akq * 4 + 2) * 128 + arow] = wv.z;
        sA[(akq * 4 + 3) * 128 + arow] = wv.w;
        *(float4*)&sB[bk * 128 + bj] = xv;
        __syncthreads();
#pragma unroll
        for (int kk = 0; kk < 8; kk++) {
            float4 a0 = sA4[kk * 32 + ty * 2];
            float4 a1 = sA4[kk * 32 + ty * 2 + 1];
            float4 b0 = sB4[kk * 32 + tx * 2];
            float4 b1 = sB4[kk * 32 + tx * 2 + 1];
            float av[8] = { a0.x, a0.y, a0.z, a0.w, a1.x, a1.y, a1.z, a1.w };
            float bv[8] = { b0.x, b0.y, b0.z, b0.w, b1.x, b1.y, b1.z, b1.w };
#pragma unroll
            for (int i = 0; i < 8; i++)
#pragma unroll
                for (int j = 0; j < 8; j++)
                    acc[i][j] += av[i] * bv[j];
        }
    }

    float* outp = g_y + (size_t)b * C * NN + n0;
    float lsum = 0.f, lsq = 0.f;
#pragma unroll
    for (int i = 0; i < 8; i++) {
        int r = r0 + i;
        float bb = bo[r];
#pragma unroll
        for (int j = 0; j < 8; j++) {
            acc[i][j] += bb;
            lsum += acc[i][j];
            lsq  += acc[i][j] * acc[i][j];
        }
        *(float4*)&outp[(size_t)r * NN + c0] =
            make_float4(acc[i][0], acc[i][1], acc[i][2], acc[i][3]);
        *(float4*)&outp[(size_t)r * NN + c0 + 4] =
            make_float4(acc[i][4], acc[i][5], acc[i][6], acc[i][7]);
    }
    const int w = tid >> 5, lane = tid & 31;
#pragma unroll
    for (int o = 16; o; o >>= 1) {
        lsum += __shfl_xor_sync(0xffffffffu, lsum, o);
        lsq  += __shfl_xor_sync(0xffffffffu, lsq,  o);
    }
    if (lane == 0) { redS[w] = lsum; redQ[w] = lsq; }
    __syncthreads();
    if (tid == 0) {
        float s = 0.f, q = 0.f;
#pragma unroll
        for (int i = 0; i < 8; i++) { s += redS[i]; q += redQ[i]; }
        atomicAdd(&g_sum[b], s);
        atomicAdd(&g_sumsq[b], q);
    }
}

// ---------------- K5: GroupNorm, float4 ----------------
__global__ void __launch_bounds__(256) k5_norm(
    const float* __restrict__ gn_w, const float* __restrict__ gn_b,
    float* __restrict__ out)
{
    int i4 = blockIdx.x * 256 + threadIdx.x;
    int b = i4 >> 17;
    int c = (i4 >> 10) & 127;
    const float cn = (float)(C * NN);
    float mu = g_sum[b] / cn;
    float var = g_sumsq[b] / cn - mu * mu;
    float is = rsqrtf(var + GEPS);
    float w = gn_w[c] * is, bb = gn_b[c] - mu * w;
    float4 v = *(const float4*)&g_y[(size_t)i4 * 4];
    v.x = v.x * w + bb; v.y = v.y * w + bb;
    v.z = v.z * w + bb; v.w = v.w * w + bb;
    *(float4*)&out[(size_t)i4 * 4] = v;
}

// ---------------- launch ----------------
extern "C" void kernel_launch(void* const* d_in, const int* in_sizes, int n_in,
                              void* d_out, int out_size)
{
    const float* x  = (const float*)d_in[0];
    const float* Wq = (const float*)d_in[1];
    const float* Wk = (const float*)d_in[2];
    const float* Wv = (const float*)d_in[3];
    const float* Wo = (const float*)d_in[4];
    const float* bo = (const float*)d_in[5];
    const float* gw = (const float*)d_in[6];
    const float* gb = (const float*)d_in[7];
    float* out = (float*)d_out;

    static int smem_set = 0;
    const int K1_SMEM = 128 * 132 * 4;   // 67584 B staging (>= 8KB mainloop needs)
    if (!smem_set) {
        cudaFuncSetAttribute(k1_proj, cudaFuncAttributeMaxDynamicSharedMemorySize, K1_SMEM);
        smem_set = 1;
    }

    k0_zero<<<132, 256>>>();
    k1_proj<<<dim3(32, 3, 32), 256, K1_SMEM>>>(x, Wq, Wk, Wv);
    k2_ctx<<<dim3(8, 128), 256>>>();
    k3_fold<<<dim3(4, 32), 256>>>(Wo);
    k4_out<<<dim3(32, 32), 256>>>(bo);
    k5_norm<<<16384, 256>>>(gw, gb, out);
}

// round 4
// speedup vs baseline: 2.1596x; 1.4590x over previous
#include <cuda_runtime.h>
#include <math.h>

#define B 32
#define C 128
#define NN 4096
#define HEADS 4
#define DH 32
#define HIDDEN 128
#define QSCALE 0.17677669529663687f   /* 32^-0.5 */
#define GEPS 1e-5f

// ---------------- scratch ----------------
__device__ float g_qkv[(size_t)B * 384 * NN];  // 0-127 q (softmaxed), 128-255 k, 256-383 v
__device__ float g_ctx[B * HEADS * DH * DH];   // unnormalized ctx partials
__device__ float g_rsum[B * HIDDEN];           // per (b, row) sum of exp(k)
__device__ float g_M[B * HIDDEN * HIDDEN];
__device__ float g_y[(size_t)B * C * NN];
__device__ float g_sum[B];
__device__ float g_sumsq[B];

__device__ __forceinline__ float cvt_tf32(float x) {
    asm("cvt.rna.tf32.f32 %0, %0;" : "+f"(x));
    return x;
}

__device__ __forceinline__ void mma_tf32(float* d, const float* a, const float* b) {
    asm("mma.sync.aligned.m16n8k8.row.col.f32.tf32.tf32.f32 "
        "{%0,%1,%2,%3}, {%4,%5,%6,%7}, {%8,%9}, {%0,%1,%2,%3};"
        : "+f"(d[0]), "+f"(d[1]), "+f"(d[2]), "+f"(d[3])
        : "f"(a[0]), "f"(a[1]), "f"(a[2]), "f"(a[3]), "f"(b[0]), "f"(b[1]));
}

// ---------------- K0: zero accumulators ----------------
__global__ void __launch_bounds__(256) k0_zero() {
    int gid = blockIdx.x * 256 + threadIdx.x;
    float4 z = make_float4(0.f, 0.f, 0.f, 0.f);
    if (gid < 32768) ((float4*)g_ctx)[gid] = z;
    if (gid < 1024)  ((float4*)g_rsum)[gid] = z;
    if (gid < 32) { g_sum[gid] = 0.f; g_sumsq[gid] = 0.f; }
}

// ---------------- K1: tf32 mma qkv projection + fused q softmax ----------------
// grid (32 ncol, 3 rowtile, 32 b), 256 threads (8 warps, 2x4)
// block tile 128x128, K=128; smem slabs [16][132] transposed A + B
__global__ void __launch_bounds__(256) k1_proj(
    const float* __restrict__ x,
    const float* __restrict__ Wq,
    const float* __restrict__ Wk,
    const float* __restrict__ Wv)
{
    extern __shared__ float smem[];
    float* sA = smem;            // [16 k][132] rows
    float* sB = smem + 2112;     // [16 k][132] cols
    float* stage = smem;         // reused [128][132] for q epilogue

    const int b  = blockIdx.z;
    const int rowtile = blockIdx.y;
    const int n0 = blockIdx.x * 128;
    const int tid = threadIdx.x;
    const int lane = tid & 31, wid = tid >> 5;
    const int mbase = (wid >> 2) * 64, nbase = (wid & 3) * 32;
    const int gid = lane >> 2, tig = lane & 3;

    const float* Wp = (rowtile == 0) ? Wq : ((rowtile == 1) ? Wk : Wv);
    const float* xb = x + (size_t)b * C * NN + n0;

    const int arow = tid & 127, ah = tid >> 7;   // A loader
    const int bk = tid >> 4, bn = (tid & 15) * 8; // B loader

    float d[4][4][4];
#pragma unroll
    for (int mt = 0; mt < 4; mt++)
#pragma unroll
        for (int nt = 0; nt < 4; nt++)
#pragma unroll
            for (int r = 0; r < 4; r++) d[mt][nt][r] = 0.f;

    for (int kt = 0; kt < 8; kt++) {
        const int k0 = kt * 16;
        float4 w0 = *(const float4*)&Wp[arow * 128 + k0 + ah * 8];
        float4 w1 = *(const float4*)&Wp[arow * 128 + k0 + ah * 8 + 4];
        float4 x0 = *(const float4*)&xb[(size_t)(k0 + bk) * NN + bn];
        float4 x1 = *(const float4*)&xb[(size_t)(k0 + bk) * NN + bn + 4];
        __syncthreads();
        sA[(ah * 8 + 0) * 132 + arow] = cvt_tf32(w0.x);
        sA[(ah * 8 + 1) * 132 + arow] = cvt_tf32(w0.y);
        sA[(ah * 8 + 2) * 132 + arow] = cvt_tf32(w0.z);
        sA[(ah * 8 + 3) * 132 + arow] = cvt_tf32(w0.w);
        sA[(ah * 8 + 4) * 132 + arow] = cvt_tf32(w1.x);
        sA[(ah * 8 + 5) * 132 + arow] = cvt_tf32(w1.y);
        sA[(ah * 8 + 6) * 132 + arow] = cvt_tf32(w1.z);
        sA[(ah * 8 + 7) * 132 + arow] = cvt_tf32(w1.w);
        float* bp = &sB[bk * 132 + bn];
        bp[0] = cvt_tf32(x0.x); bp[1] = cvt_tf32(x0.y);
        bp[2] = cvt_tf32(x0.z); bp[3] = cvt_tf32(x0.w);
        bp[4] = cvt_tf32(x1.x); bp[5] = cvt_tf32(x1.y);
        bp[6] = cvt_tf32(x1.z); bp[7] = cvt_tf32(x1.w);
        __syncthreads();
#pragma unroll
        for (int ks = 0; ks < 16; ks += 8) {
            float a[4][4], bf[4][2];
#pragma unroll
            for (int mt = 0; mt < 4; mt++) {
                int row = mbase + mt * 16 + gid;
                a[mt][0] = sA[(ks + tig) * 132 + row];
                a[mt][1] = sA[(ks + tig) * 132 + row + 8];
                a[mt][2] = sA[(ks + tig + 4) * 132 + row];
                a[mt][3] = sA[(ks + tig + 4) * 132 + row + 8];
            }
#pragma unroll
            for (int nt = 0; nt < 4; nt++) {
                int col = nbase + nt * 8 + gid;
                bf[nt][0] = sB[(ks + tig) * 132 + col];
                bf[nt][1] = sB[(ks + tig + 4) * 132 + col];
            }
#pragma unroll
            for (int mt = 0; mt < 4; mt++)
#pragma unroll
                for (int nt = 0; nt < 4; nt++)
                    mma_tf32(d[mt][nt], a[mt], bf[nt]);
        }
    }

    if (rowtile != 0) {
        float* outp = g_qkv + ((size_t)b * 384 + rowtile * 128) * NN + n0;
#pragma unroll
        for (int mt = 0; mt < 4; mt++) {
#pragma unroll
            for (int nt = 0; nt < 4; nt++) {
                int row = mbase + mt * 16 + gid;
                int col = nbase + nt * 8 + tig * 2;
                *(float2*)&outp[(size_t)row * NN + col] =
                    make_float2(d[mt][nt][0], d[mt][nt][1]);
                *(float2*)&outp[(size_t)(row + 8) * NN + col] =
                    make_float2(d[mt][nt][2], d[mt][nt][3]);
            }
        }
        return;
    }

    // q: stage -> softmax over d per (h, col) -> coalesced global write
    __syncthreads();
#pragma unroll
    for (int mt = 0; mt < 4; mt++) {
#pragma unroll
        for (int nt = 0; nt < 4; nt++) {
            int row = mbase + mt * 16 + gid;
            int col = nbase + nt * 8 + tig * 2;
            *(float2*)&stage[row * 132 + col] = make_float2(d[mt][nt][0], d[mt][nt][1]);
            *(float2*)&stage[(row + 8) * 132 + col] = make_float2(d[mt][nt][2], d[mt][nt][3]);
        }
    }
    __syncthreads();

    float* outq = g_qkv + (size_t)b * 384 * NN + n0;
#pragma unroll
    for (int t = tid; t < 512; t += 256) {
        const int col = t & 127;
        const int h = t >> 7;
        float sum = 0.f;
#pragma unroll
        for (int dd = 0; dd < 32; dd++) {
            float* p = &stage[(h * 32 + dd) * 132 + col];
            float e = __expf(*p);
            *p = e;
            sum += e;
        }
        float inv = QSCALE / sum;
#pragma unroll
        for (int dd = 0; dd < 32; dd++)
            outq[(size_t)(h * 32 + dd) * NN + col] = stage[(h * 32 + dd) * 132 + col] * inv;
    }
}

// ---------------- K2: partial ctx = exp(k) @ v^T + partial rowsum ----------------
// grid (8 chunks, 128 bh), 256 threads; atomics into g_ctx/g_rsum
__global__ void __launch_bounds__(256) k2_ctx()
{
    const int bh = blockIdx.y;
    const int b = bh >> 2, h = bh & 3;
    const int cbase = blockIdx.x * 512;
    const float* kb = g_qkv + ((size_t)b * 384 + 128 + h * 32) * NN + cbase;
    const float* vb = g_qkv + ((size_t)b * 384 + 256 + h * 32) * NN + cbase;

    __shared__ float sK[32 * 128];
    __shared__ float sVT[128 * 36];

    const int tid = threadIdx.x;
    const int d  = tid >> 3;
    const int e0 = (tid & 7) * 4;
    const int ld_row = tid >> 3;
    const int ld_c   = (tid & 7) * 16;

    float4 acc = make_float4(0.f, 0.f, 0.f, 0.f);
    float lsum = 0.f;

    for (int c0 = 0; c0 < 512; c0 += 128) {
        __syncthreads();
        {
            const float* kr = kb + (size_t)ld_row * NN + c0 + ld_c;
#pragma unroll
            for (int q4 = 0; q4 < 4; q4++) {
                float4 t = *(const float4*)(kr + q4 * 4);
                float e0v = __expf(t.x), e1v = __expf(t.y);
                float e2v = __expf(t.z), e3v = __expf(t.w);
                int base = ld_row * 128 + ld_c + q4 * 4;
                sK[base + 0] = e0v; sK[base + 1] = e1v;
                sK[base + 2] = e2v; sK[base + 3] = e3v;
                lsum += e0v + e1v + e2v + e3v;
            }
            const float* vr = vb + (size_t)ld_row * NN + c0 + ld_c;
#pragma unroll
            for (int q4 = 0; q4 < 4; q4++) {
                float4 t = *(const float4*)(vr + q4 * 4);
                int nc = ld_c + q4 * 4;
                sVT[(nc + 0) * 36 + ld_row] = t.x;
                sVT[(nc + 1) * 36 + ld_row] = t.y;
                sVT[(nc + 2) * 36 + ld_row] = t.z;
                sVT[(nc + 3) * 36 + ld_row] = t.w;
            }
        }
        __syncthreads();
#pragma unroll 4
        for (int n = 0; n < 128; n++) {
            float kd = sK[d * 128 + n];
            float4 vv = *(const float4*)&sVT[n * 36 + e0];
            acc.x += kd * vv.x; acc.y += kd * vv.y;
            acc.z += kd * vv.z; acc.w += kd * vv.w;
        }
    }

#pragma unroll
    for (int o = 4; o; o >>= 1) lsum += __shfl_xor_sync(0xffffffffu, lsum, o);
    if ((tid & 7) == 0)
        atomicAdd(&g_rsum[b * HIDDEN + h * 32 + ld_row], lsum);

    float* cp = &g_ctx[((size_t)bh * 32 + d) * 32 + e0];
    atomicAdd(cp + 0, acc.x);
    atomicAdd(cp + 1, acc.y);
    atomicAdd(cp + 2, acc.z);
    atomicAdd(cp + 3, acc.w);
}

// ---------------- K3: M_b = Wo @ blockdiag(ctx^T / rsum) ----------------
// grid (8, 32): 16 o-rows per block, 8 cols per thread
__global__ void __launch_bounds__(256) k3_fold(const float* __restrict__ Wo)
{
    const int b = blockIdx.y;
    const int og = blockIdx.x * 16;
    __shared__ float sctx[HEADS * DH * DH];
    __shared__ float sinv[HIDDEN];
    const int tid = threadIdx.x;
#pragma unroll
    for (int rr = 0; rr < 4; rr++) {
        int idx = tid + rr * 256;
        *(float4*)&sctx[idx * 4] = *(const float4*)&g_ctx[(size_t)b * 4096 + idx * 4];
    }
    if (tid < 128) sinv[tid] = 1.0f / g_rsum[b * HIDDEN + tid];
    __syncthreads();

    const int o = og + (tid >> 4);
    const int colg = (tid & 15) * 8;
    const int h = colg >> 5;

    float wo[32];
#pragma unroll
    for (int q4 = 0; q4 < 8; q4++) {
        float4 t = *(const float4*)&Wo[o * 128 + h * 32 + q4 * 4];
        wo[q4 * 4 + 0] = t.x; wo[q4 * 4 + 1] = t.y;
        wo[q4 * 4 + 2] = t.z; wo[q4 * 4 + 3] = t.w;
    }
    float* Mout = g_M + (size_t)b * HIDDEN * HIDDEN + o * HIDDEN;
#pragma unroll
    for (int cc = 0; cc < 8; cc++) {
        int col = colg + cc;
        int dd = col & 31;
        float s = 0.f;
#pragma unroll
        for (int q4 = 0; q4 < 8; q4++) {
            float4 cv = *(const float4*)&sctx[(h * 32 + dd) * 32 + q4 * 4];
            s += wo[q4 * 4 + 0] * cv.x + wo[q4 * 4 + 1] * cv.y
               + wo[q4 * 4 + 2] * cv.z + wo[q4 * 4 + 3] * cv.w;
        }
        Mout[col] = s * sinv[col];
    }
}

// ---------------- K4: tf32 mma y = M_b @ softq + bo, + stats ----------------
// grid (32 ncol, 32 b), 256 threads
__global__ void __launch_bounds__(256) k4_out(const float* __restrict__ bo)
{
    __shared__ float sA[16 * 132];
    __shared__ float sB[16 * 132];
    __shared__ float redS[8], redQ[8];

    const int b  = blockIdx.y;
    const int n0 = blockIdx.x * 128;
    const int tid = threadIdx.x;
    const int lane = tid & 31, wid = tid >> 5;
    const int mbase = (wid >> 2) * 64, nbase = (wid & 3) * 32;
    const int gid = lane >> 2, tig = lane & 3;

    const float* Mb = g_M + (size_t)b * HIDDEN * HIDDEN;
    const float* qb = g_qkv + (size_t)b * 384 * NN + n0;

    const int arow = tid & 127, ah = tid >> 7;
    const int bk = tid >> 4, bn = (tid & 15) * 8;

    float d[4][4][4];
#pragma unroll
    for (int mt = 0; mt < 4; mt++)
#pragma unroll
        for (int nt = 0; nt < 4; nt++)
#pragma unroll
            for (int r = 0; r < 4; r++) d[mt][nt][r] = 0.f;

    for (int kt = 0; kt < 8; kt++) {
        const int k0 = kt * 16;
        float4 w0 = *(const float4*)&Mb[arow * 128 + k0 + ah * 8];
        float4 w1 = *(const float4*)&Mb[arow * 128 + k0 + ah * 8 + 4];
        float4 x0 = *(const float4*)&qb[(size_t)(k0 + bk) * NN + bn];
        float4 x1 = *(const float4*)&qb[(size_t)(k0 + bk) * NN + bn + 4];
        __syncthreads();
        sA[(ah * 8 + 0) * 132 + arow] = cvt_tf32(w0.x);
        sA[(ah * 8 + 1) * 132 + arow] = cvt_tf32(w0.y);
        sA[(ah * 8 + 2) * 132 + arow] = cvt_tf32(w0.z);
        sA[(ah * 8 + 3) * 132 + arow] = cvt_tf32(w0.w);
        sA[(ah * 8 + 4) * 132 + arow] = cvt_tf32(w1.x);
        sA[(ah * 8 + 5) * 132 + arow] = cvt_tf32(w1.y);
        sA[(ah * 8 + 6) * 132 + arow] = cvt_tf32(w1.z);
        sA[(ah * 8 + 7) * 132 + arow] = cvt_tf32(w1.w);
        float* bp = &sB[bk * 132 + bn];
        bp[0] = cvt_tf32(x0.x); bp[1] = cvt_tf32(x0.y);
        bp[2] = cvt_tf32(x0.z); bp[3] = cvt_tf32(x0.w);
        bp[4] = cvt_tf32(x1.x); bp[5] = cvt_tf32(x1.y);
        bp[6] = cvt_tf32(x1.z); bp[7] = cvt_tf32(x1.w);
        __syncthreads();
#pragma unroll
        for (int ks = 0; ks < 16; ks += 8) {
            float a[4][4], bf[4][2];
#pragma unroll
            for (int mt = 0; mt < 4; mt++) {
                int row = mbase + mt * 16 + gid;
                a[mt][0] = sA[(ks + tig) * 132 + row];
                a[mt][1] = sA[(ks + tig) * 132 + row + 8];
                a[mt][2] = sA[(ks + tig + 4) * 132 + row];
                a[mt][3] = sA[(ks + tig + 4) * 132 + row + 8];
            }
#pragma unroll
            for (int nt = 0; nt < 4; nt++) {
                int col = nbase + nt * 8 + gid;
                bf[nt][0] = sB[(ks + tig) * 132 + col];
                bf[nt][1] = sB[(ks + tig + 4) * 132 + col];
            }
#pragma unroll
            for (int mt = 0; mt < 4; mt++)
#pragma unroll
                for (int nt = 0; nt < 4; nt++)
                    mma_tf32(d[mt][nt], a[mt], bf[nt]);
        }
    }

    float* outp = g_y + (size_t)b * C * NN + n0;
    float lsum = 0.f, lsq = 0.f;
#pragma unroll
    for (int mt = 0; mt < 4; mt++) {
        int row = mbase + mt * 16 + gid;
        float bb0 = bo[row], bb8 = bo[row + 8];
#pragma unroll
        for (int nt = 0; nt < 4; nt++) {
            int col = nbase + nt * 8 + tig * 2;
            float v0 = d[mt][nt][0] + bb0, v1 = d[mt][nt][1] + bb0;
            float v2 = d[mt][nt][2] + bb8, v3 = d[mt][nt][3] + bb8;
            *(float2*)&outp[(size_t)row * NN + col] = make_float2(v0, v1);
            *(float2*)&outp[(size_t)(row + 8) * NN + col] = make_float2(v2, v3);
            lsum += v0 + v1 + v2 + v3;
            lsq  += v0 * v0 + v1 * v1 + v2 * v2 + v3 * v3;
        }
    }
    const int w = tid >> 5;
#pragma unroll
    for (int o = 16; o; o >>= 1) {
        lsum += __shfl_xor_sync(0xffffffffu, lsum, o);
        lsq  += __shfl_xor_sync(0xffffffffu, lsq,  o);
    }
    if (lane == 0) { redS[w] = lsum; redQ[w] = lsq; }
    __syncthreads();
    if (tid == 0) {
        float s = 0.f, q = 0.f;
#pragma unroll
        for (int i = 0; i < 8; i++) { s += redS[i]; q += redQ[i]; }
        atomicAdd(&g_sum[b], s);
        atomicAdd(&g_sumsq[b], q);
    }
}

// ---------------- K5: GroupNorm, float4 ----------------
__global__ void __launch_bounds__(256) k5_norm(
    const float* __restrict__ gn_w, const float* __restrict__ gn_b,
    float* __restrict__ out)
{
    int i4 = blockIdx.x * 256 + threadIdx.x;
    int b = i4 >> 17;
    int c = (i4 >> 10) & 127;
    const float cn = (float)(C * NN);
    float mu = g_sum[b] / cn;
    float var = g_sumsq[b] / cn - mu * mu;
    float is = rsqrtf(var + GEPS);
    float w = gn_w[c] * is, bb = gn_b[c] - mu * w;
    float4 v = *(const float4*)&g_y[(size_t)i4 * 4];
    v.x = v.x * w + bb; v.y = v.y * w + bb;
    v.z = v.z * w + bb; v.w = v.w * w + bb;
    *(float4*)&out[(size_t)i4 * 4] = v;
}

// ---------------- launch ----------------
extern "C" void kernel_launch(void* const* d_in, const int* in_sizes, int n_in,
                              void* d_out, int out_size)
{
    const float* x  = (const float*)d_in[0];
    const float* Wq = (const float*)d_in[1];
    const float* Wk = (const float*)d_in[2];
    const float* Wv = (const float*)d_in[3];
    const float* Wo = (const float*)d_in[4];
    const float* bo = (const float*)d_in[5];
    const float* gw = (const float*)d_in[6];
    const float* gb = (const float*)d_in[7];
    float* out = (float*)d_out;

    static int smem_set = 0;
    const int K1_SMEM = 128 * 132 * 4;   // 67584 B: q staging (mainloop needs 16.9KB)
    if (!smem_set) {
        cudaFuncSetAttribute(k1_proj, cudaFuncAttributeMaxDynamicSharedMemorySize, K1_SMEM);
        smem_set = 1;
    }

    k0_zero<<<132, 256>>>();
    k1_proj<<<dim3(32, 3, 32), 256, K1_SMEM>>>(x, Wq, Wk, Wv);
    k2_ctx<<<dim3(8, 128), 256>>>();
    k3_fold<<<dim3(8, 32), 256>>>(Wo);
    k4_out<<<dim3(32, 32), 256>>>(bo);
    k5_norm<<<16384, 256>>>(gw, gb, out);
}